// round 7
// baseline (speedup 1.0000x reference)
#include <cuda_runtime.h>
#include <cstdint>

// Problem constants (fixed shapes from setup_inputs)
#define TT 64
#define BB 4096
#define DD 32
#define HH 5
#define GG 20      // 4*H gates
#define VV 10
#define IN 128

#define BLK 256
#define ITEMS 128                   // b's per block (2 threads per item)
#define NCHUNK (BB / ITEMS)         // 32 b-chunks
#define LPAD 12                     // padded half-row (10 used), 48B => 16B aligned

// Per-b precomputed terms (transposed [g][B] for coalesced access), L2-resident.
__device__ float g_hb0[GG * BB];
__device__ float g_hb1[GG * BB];
__device__ float g_c0[HH * BB];
__device__ float g_c1[HH * BB];

__device__ __forceinline__ float sigm(float v) {
    return __fdividef(1.0f, 1.0f + __expf(-v));
}
__device__ __forceinline__ float tanh_(float v) {
    return 1.0f - __fdividef(2.0f, __expf(2.0f * v) + 1.0f);
}

// ---------------------------------------------------------------------------
// Kernel 1: per-b precompute of h@W_hh^T + biases, and cell transpose.
// ---------------------------------------------------------------------------
__global__ void prep_kernel(const float* __restrict__ hidden,
                            const float* __restrict__ cell,
                            const float* __restrict__ W_hh0,
                            const float* __restrict__ b_ih0,
                            const float* __restrict__ b_hh0,
                            const float* __restrict__ W_hh1,
                            const float* __restrict__ b_ih1,
                            const float* __restrict__ b_hh1) {
    int b = blockIdx.x * blockDim.x + threadIdx.x;
    if (b >= BB) return;

    float h0[HH], h1[HH];
#pragma unroll
    for (int k = 0; k < HH; k++) {
        h0[k] = hidden[b * HH + k];
        h1[k] = hidden[BB * HH + b * HH + k];
    }
#pragma unroll
    for (int g = 0; g < GG; g++) {
        float s0 = b_ih0[g] + b_hh0[g];
        float s1 = b_ih1[g] + b_hh1[g];
#pragma unroll
        for (int k = 0; k < HH; k++) {
            s0 = fmaf(h0[k], W_hh0[g * HH + k], s0);
            s1 = fmaf(h1[k], W_hh1[g * HH + k], s1);
        }
        g_hb0[g * BB + b] = s0;
        g_hb1[g * BB + b] = s1;
    }
#pragma unroll
    for (int k = 0; k < HH; k++) {
        g_c0[k * BB + b] = cell[b * HH + k];
        g_c1[k * BB + b] = cell[BB * HH + b * HH + k];
    }
}

// ---------------------------------------------------------------------------
// Kernel 2: gate-split main kernel.
//   Phase A: 256 threads = 128 items x 2 gate-halves. Each thread computes
//            10 gate pre-activations (acc[10], x streamed one float4 at a
//            time) -> low registers -> 4 CTAs/SM.
//   Phase B: 128 threads run the LSTM epilogue (both cells) per item.
//   blockIdx.x = b-chunk (32), blockIdx.y = t (64).
// ---------------------------------------------------------------------------
__global__ void __launch_bounds__(BLK, 4)
decoder_kernel(const float* __restrict__ dec_x,
               const int*   __restrict__ id1,
               const int*   __restrict__ id2,
               const int*   __restrict__ id3,
               const float* __restrict__ embed,
               const float* __restrict__ W_ih0,
               const float* __restrict__ W_ih1,
               float* __restrict__ out) {
    __shared__ __align__(16) float sWa[GG * DD];            // W_ih0[:,0:32] (f4 rows)
    __shared__ __align__(16) float sLut[2 * 3 * VV * LPAD]; // [half][j][v][12]
    __shared__ __align__(16) float sW1t[HH * GG];           // W_ih1^T [k][g]
    __shared__ __align__(16) float sGate[2 * ITEMS * LPAD]; // [half][item][12]
    __shared__ __align__(16) float sOut[ITEMS * HH];        // output staging

    const int tid = threadIdx.x;

    // ---- cooperative shared fill ----
    for (int i = tid; i < GG * DD; i += BLK) {
        int g = i >> 5, k = i & 31;
        sWa[i] = W_ih0[g * IN + k];
    }
    for (int i = tid; i < HH * GG; i += BLK) {
        int k = i / GG, g = i - k * GG;
        sW1t[i] = W_ih1[g * HH + k];
    }
    // LUT[half][j][v][jg] = embed[v] . W_ih0[half*10+jg, 32+32j : 64+32j]
    for (int i = tid; i < 2 * 3 * VV * VV; i += BLK) {  // 600 entries
        int jg   = i % VV;          // 0..9 (gate within half)
        int r    = i / VV;
        int v    = r % VV;
        r        = r / VV;
        int j    = r % 3;
        int half = r / 3;
        int g    = half * 10 + jg;
        const float* e = embed + v * DD;
        const float* w = W_ih0 + g * IN + DD + DD * j;
        float s = 0.0f;
#pragma unroll
        for (int k = 0; k < DD; k++) s = fmaf(e[k], w[k], s);
        sLut[((half * 3 + j) * VV + v) * LPAD + jg] = s;
    }
    __syncthreads();

    const int t    = blockIdx.y;
    const int item = tid & (ITEMS - 1);
    const int half = tid >> 7;            // 0 or 1
    const int gb   = half * 10;           // gate base
    const int b    = blockIdx.x * ITEMS + item;
    const int tb   = t * BB + b;

    // ================= Phase A: 10 gate pre-activations =================
    float acc[10];
#pragma unroll
    for (int j = 0; j < 10; j++)
        acc[j] = g_hb0[(gb + j) * BB + b];          // coalesced (b consecutive)

    // embedding LUT adds (f4,f4,f2 from padded half-rows)
    {
        const int i1 = id1[tb], i2 = id2[tb], i3 = id3[tb];
        const float* l1 = sLut + ((half * 3 + 0) * VV + i1) * LPAD;
        const float* l2 = sLut + ((half * 3 + 1) * VV + i2) * LPAD;
        const float* l3 = sLut + ((half * 3 + 2) * VV + i3) * LPAD;
#pragma unroll
        for (int q = 0; q < 2; q++) {
            float4 a = ((const float4*)l1)[q];
            float4 c = ((const float4*)l2)[q];
            float4 d = ((const float4*)l3)[q];
            acc[4 * q + 0] += a.x + c.x + d.x;
            acc[4 * q + 1] += a.y + c.y + d.y;
            acc[4 * q + 2] += a.z + c.z + d.z;
            acc[4 * q + 3] += a.w + c.w + d.w;
        }
        float2 a = ((const float2*)l1)[4];
        float2 c = ((const float2*)l2)[4];
        float2 d = ((const float2*)l3)[4];
        acc[8] += a.x + c.x + d.x;
        acc[9] += a.y + c.y + d.y;
    }

    // dec_x @ Wa^T : k-outer, one x float4 live at a time; weight LDS.128
    // is a warp-wide broadcast (all lanes same half => same address).
    {
        const float4* xp = (const float4*)(dec_x + (size_t)tb * DD);
#pragma unroll
        for (int q = 0; q < DD / 4; q++) {
            float4 x = xp[q];
            const float4* wp = (const float4*)(sWa + gb * DD) + q;
#pragma unroll
            for (int j = 0; j < 10; j++) {
                float4 w = wp[j * (DD / 4)];
                acc[j] = fmaf(x.x, w.x, fmaf(x.y, w.y,
                         fmaf(x.z, w.z, fmaf(x.w, w.w, acc[j]))));
            }
        }
    }

    // stage gates to shared: [half][item][12], base 48B-aligned
    {
        float* gr = sGate + (half * ITEMS + item) * LPAD;
        ((float4*)gr)[0] = make_float4(acc[0], acc[1], acc[2], acc[3]);
        ((float4*)gr)[1] = make_float4(acc[4], acc[5], acc[6], acc[7]);
        ((float2*)gr)[4] = make_float2(acc[8], acc[9]);
    }
    __syncthreads();

    // ================= Phase B: LSTM epilogue (128 threads) =============
    if (tid < ITEMS) {
        const int eb  = blockIdx.x * ITEMS + tid;

        // gather the 20 gates of this item
        float hg[GG];
        {
            const float* r0 = sGate + tid * LPAD;                // gates 0..9
            const float* r1 = sGate + (ITEMS + tid) * LPAD;      // gates 10..19
            float4 a = ((const float4*)r0)[0];
            float4 c = ((const float4*)r0)[1];
            float2 d = ((const float2*)r0)[4];
            hg[0] = a.x; hg[1] = a.y; hg[2] = a.z; hg[3] = a.w;
            hg[4] = c.x; hg[5] = c.y; hg[6] = c.z; hg[7] = c.w;
            hg[8] = d.x; hg[9] = d.y;
            a = ((const float4*)r1)[0];
            c = ((const float4*)r1)[1];
            d = ((const float2*)r1)[4];
            hg[10] = a.x; hg[11] = a.y; hg[12] = a.z; hg[13] = a.w;
            hg[14] = c.x; hg[15] = c.y; hg[16] = c.z; hg[17] = c.w;
            hg[18] = d.x; hg[19] = d.y;
        }

        // cell 0 (gate order i, f, g, o)
        float h1[HH];
#pragma unroll
        for (int k = 0; k < HH; k++) {
            float ig = sigm(hg[k]);
            float fg = sigm(hg[HH + k]);
            float gg = tanh_(hg[2 * HH + k]);
            float og = sigm(hg[3 * HH + k]);
            float c  = fmaf(fg, g_c0[k * BB + eb], ig * gg);
            h1[k] = og * tanh_(c);
        }

        // layer-1 gates: hb1 + h1 @ W_ih1^T (k-outer, f4 weights)
        float a1[GG];
#pragma unroll
        for (int g = 0; g < GG; g++) a1[g] = g_hb1[g * BB + eb];
#pragma unroll
        for (int k = 0; k < HH; k++) {
            const float4* wp = (const float4*)(sW1t + k * GG);
            float hv = h1[k];
#pragma unroll
            for (int q = 0; q < GG / 4; q++) {
                float4 w = wp[q];
                a1[4 * q + 0] = fmaf(hv, w.x, a1[4 * q + 0]);
                a1[4 * q + 1] = fmaf(hv, w.y, a1[4 * q + 1]);
                a1[4 * q + 2] = fmaf(hv, w.z, a1[4 * q + 2]);
                a1[4 * q + 3] = fmaf(hv, w.w, a1[4 * q + 3]);
            }
        }

        // cell 1 -> staged output
#pragma unroll
        for (int k = 0; k < HH; k++) {
            float ig = sigm(a1[k]);
            float fg = sigm(a1[HH + k]);
            float gg = tanh_(a1[2 * HH + k]);
            float og = sigm(a1[3 * HH + k]);
            float c  = fmaf(fg, g_c1[k * BB + eb], ig * gg);
            sOut[tid * HH + k] = og * tanh_(c);
        }
    }
    __syncthreads();

    // coalesced store of the block's [128, 5] output slab (640 floats)
    float* ob = out + (size_t)t * BB * HH + (size_t)blockIdx.x * ITEMS * HH;
    for (int i = tid; i < ITEMS * HH; i += BLK) ob[i] = sOut[i];
}

// ---------------------------------------------------------------------------
// Launch
// Input order: 0 horizon, 1 hidden, 2 cell, 3 dec_x, 4 mote_id_cat,
// 5 fault_type_cat, 6 mote_fault_cat, 7 mote_embed, 8 W_ih0, 9 W_hh0,
// 10 b_ih0, 11 b_hh0, 12 W_ih1, 13 W_hh1, 14 b_ih1, 15 b_hh1
// ---------------------------------------------------------------------------
extern "C" void kernel_launch(void* const* d_in, const int* in_sizes, int n_in,
                              void* d_out, int out_size) {
    const float* hidden = (const float*)d_in[1];
    const float* cell   = (const float*)d_in[2];
    const float* dec_x  = (const float*)d_in[3];
    const int*   id1    = (const int*)d_in[4];
    const int*   id2    = (const int*)d_in[5];
    const int*   id3    = (const int*)d_in[6];
    const float* embed  = (const float*)d_in[7];
    const float* W_ih0  = (const float*)d_in[8];
    const float* W_hh0  = (const float*)d_in[9];
    const float* b_ih0  = (const float*)d_in[10];
    const float* b_hh0  = (const float*)d_in[11];
    const float* W_ih1  = (const float*)d_in[12];
    const float* W_hh1  = (const float*)d_in[13];
    const float* b_ih1  = (const float*)d_in[14];
    const float* b_hh1  = (const float*)d_in[15];
    float* out = (float*)d_out;

    prep_kernel<<<BB / BLK, BLK>>>(hidden, cell, W_hh0, b_ih0, b_hh0,
                                   W_hh1, b_ih1, b_hh1);

    dim3 grid(NCHUNK, TT);
    decoder_kernel<<<grid, BLK>>>(dec_x, id1, id2, id3, embed,
                                  W_ih0, W_ih1, out);
}

// round 8
// speedup vs baseline: 3.0252x; 3.0252x over previous
#include <cuda_runtime.h>
#include <cstdint>

// Problem constants (fixed shapes from setup_inputs)
#define TT 64
#define BB 4096
#define DD 32
#define HH 5
#define GG 20      // 4*H gates
#define VV 10
#define IN 128

#define BLK 256
#define NCHUNK (BB / BLK)           // 16 b-chunks

// Per-b precomputed terms (transposed [g][B] for coalesced access), L2-resident.
__device__ float g_hb0[GG * BB];
__device__ float g_hb1[GG * BB];
__device__ float g_c0[HH * BB];
__device__ float g_c1[HH * BB];
__device__ float g_lut[3 * VV * GG];   // [j][v][g] embedding->gate LUT

__device__ __forceinline__ float sigm(float v) {
    return __fdividef(1.0f, 1.0f + __expf(-v));
}
__device__ __forceinline__ float tanh_(float v) {
    return 1.0f - __fdividef(2.0f, __expf(2.0f * v) + 1.0f);
}

// ---------------------------------------------------------------------------
// Kernel 1: precompute. Blocks 0..63: (b, quarter) threads computing 5 gates
// of hb0 and 5 of hb1 each + cell transpose. Block 64: the embedding LUT.
// ---------------------------------------------------------------------------
__global__ void prep_kernel(const float* __restrict__ hidden,
                            const float* __restrict__ cell,
                            const float* __restrict__ embed,
                            const float* __restrict__ W_ih0,
                            const float* __restrict__ W_hh0,
                            const float* __restrict__ b_ih0,
                            const float* __restrict__ b_hh0,
                            const float* __restrict__ W_hh1,
                            const float* __restrict__ b_ih1,
                            const float* __restrict__ b_hh1) {
    if (blockIdx.x < 64) {
        // 64 blocks x 256 threads = 16384 = 4096 b x 4 quarters
        int idx = blockIdx.x * BLK + threadIdx.x;
        int b = idx >> 2;             // 0..4095
        int q = idx & 3;              // gate quarter: gates [5q, 5q+5)
        float h0[HH], h1[HH];
#pragma unroll
        for (int k = 0; k < HH; k++) {
            h0[k] = hidden[b * HH + k];
            h1[k] = hidden[BB * HH + b * HH + k];
        }
#pragma unroll
        for (int j = 0; j < 5; j++) {
            int g = q * 5 + j;
            float s0 = b_ih0[g] + b_hh0[g];
            float s1 = b_ih1[g] + b_hh1[g];
#pragma unroll
            for (int k = 0; k < HH; k++) {
                s0 = fmaf(h0[k], W_hh0[g * HH + k], s0);
                s1 = fmaf(h1[k], W_hh1[g * HH + k], s1);
            }
            g_hb0[g * BB + b] = s0;
            g_hb1[g * BB + b] = s1;
        }
        if (q == 0) {
#pragma unroll
            for (int k = 0; k < HH; k++) {
                g_c0[k * BB + b] = cell[b * HH + k];
                g_c1[k * BB + b] = cell[BB * HH + b * HH + k];
            }
        }
    } else {
        // LUT block: 600 entries, each a 32-length dot product
        for (int i = threadIdx.x; i < 3 * VV * GG; i += BLK) {
            int j = i / (VV * GG);
            int r = i - j * (VV * GG);
            int v = r / GG;
            int g = r - v * GG;
            const float* e = embed + v * DD;
            const float* w = W_ih0 + g * IN + DD + DD * j;
            float s = 0.0f;
#pragma unroll
            for (int k = 0; k < DD; k++) s = fmaf(e[k], w[k], s);
            g_lut[i] = s;   // layout [j][v][g]
        }
    }
}

// ---------------------------------------------------------------------------
// Kernel 2: main. One thread per (t, b). IPT=1, 64-reg cap -> 4 CTAs/SM.
// Weight LDS.128 are warp-uniform broadcasts; dec_x loads fully coalesced.
//   blockIdx.x = b-chunk (16), blockIdx.y = t (64). 256 threads.
// ---------------------------------------------------------------------------
__global__ void __launch_bounds__(BLK, 4)
decoder_kernel(const float* __restrict__ dec_x,
               const int*   __restrict__ id1,
               const int*   __restrict__ id2,
               const int*   __restrict__ id3,
               const float* __restrict__ W_ih0,
               const float* __restrict__ W_ih1,
               float* __restrict__ out) {
    __shared__ __align__(16) float sWa[GG * DD];        // W_ih0[:,0:32] (f4 rows)
    __shared__ __align__(16) float sLut[3 * VV * GG];   // [j][v][g], 80B rows
    __shared__ __align__(16) float sW1t[HH * GG];       // W_ih1^T [k][g]
    __shared__ __align__(16) float sOut[BLK * HH];      // output staging

    const int tid = threadIdx.x;

    // ---- cooperative shared fill (copies only; LUT precomputed) ----
    for (int i = tid; i < GG * DD; i += BLK) {
        int g = i >> 5, k = i & 31;
        sWa[i] = W_ih0[g * IN + k];
    }
    for (int i = tid; i < HH * GG; i += BLK) {
        int k = i / GG, g = i - k * GG;
        sW1t[i] = W_ih1[g * HH + k];
    }
    for (int i = tid; i < 3 * VV * GG; i += BLK) sLut[i] = g_lut[i];
    __syncthreads();

    const int t  = blockIdx.y;
    const int b  = blockIdx.x * BLK + tid;
    const int tb = t * BB + b;

    // ---- init acc with hb0 (coalesced LDG) ----
    float acc[GG];
#pragma unroll
    for (int g = 0; g < GG; g++) acc[g] = g_hb0[g * BB + b];

    // ---- embedding LUT adds (f4 over g, 5 per row) ----
    {
        const int i1 = id1[tb], i2 = id2[tb], i3 = id3[tb];
        const float4* l1 = (const float4*)(sLut + (0 * VV + i1) * GG);
        const float4* l2 = (const float4*)(sLut + (1 * VV + i2) * GG);
        const float4* l3 = (const float4*)(sLut + (2 * VV + i3) * GG);
#pragma unroll
        for (int q = 0; q < GG / 4; q++) {
            float4 a = l1[q], c = l2[q], d = l3[q];
            acc[4 * q + 0] += a.x + c.x + d.x;
            acc[4 * q + 1] += a.y + c.y + d.y;
            acc[4 * q + 2] += a.z + c.z + d.z;
            acc[4 * q + 3] += a.w + c.w + d.w;
        }
    }

    // ---- dec_x @ Wa^T : k-outer, one x float4 live; w LDS.128 broadcast ----
    {
        const float4* xp = (const float4*)(dec_x + (size_t)tb * DD);
#pragma unroll
        for (int q = 0; q < DD / 4; q++) {
            float4 x = xp[q];
            const float4* wp = (const float4*)sWa + q;   // stride DD/4 per gate
#pragma unroll
            for (int g = 0; g < GG; g++) {
                float4 w = wp[g * (DD / 4)];
                acc[g] = fmaf(x.x, w.x, fmaf(x.y, w.y,
                         fmaf(x.z, w.z, fmaf(x.w, w.w, acc[g]))));
            }
        }
    }

    // ---- LSTM cell 0 (gate order i, f, g, o) ----
    float h1[HH];
#pragma unroll
    for (int k = 0; k < HH; k++) {
        float ig = sigm(acc[k]);
        float fg = sigm(acc[HH + k]);
        float gg = tanh_(acc[2 * HH + k]);
        float og = sigm(acc[3 * HH + k]);
        float c  = fmaf(fg, g_c0[k * BB + b], ig * gg);
        h1[k] = og * tanh_(c);
    }

    // ---- layer-1 gates: hb1 + h1 @ W_ih1^T (k-outer, f4 broadcast) ----
    float a1[GG];
#pragma unroll
    for (int g = 0; g < GG; g++) a1[g] = g_hb1[g * BB + b];
#pragma unroll
    for (int k = 0; k < HH; k++) {
        const float4* wp = (const float4*)(sW1t + k * GG);
        float hv = h1[k];
#pragma unroll
        for (int q = 0; q < GG / 4; q++) {
            float4 w = wp[q];
            a1[4 * q + 0] = fmaf(hv, w.x, a1[4 * q + 0]);
            a1[4 * q + 1] = fmaf(hv, w.y, a1[4 * q + 1]);
            a1[4 * q + 2] = fmaf(hv, w.z, a1[4 * q + 2]);
            a1[4 * q + 3] = fmaf(hv, w.w, a1[4 * q + 3]);
        }
    }

    // ---- LSTM cell 1 -> staged output ----
#pragma unroll
    for (int k = 0; k < HH; k++) {
        float ig = sigm(a1[k]);
        float fg = sigm(a1[HH + k]);
        float gg = tanh_(a1[2 * HH + k]);
        float og = sigm(a1[3 * HH + k]);
        float c  = fmaf(fg, g_c1[k * BB + b], ig * gg);
        sOut[tid * HH + k] = og * tanh_(c);
    }
    __syncthreads();

    // ---- coalesced store of the block's [256, 5] output slab ----
    float* ob = out + (size_t)t * BB * HH + (size_t)blockIdx.x * BLK * HH;
    for (int i = tid; i < BLK * HH; i += BLK) ob[i] = sOut[i];
}

// ---------------------------------------------------------------------------
// Launch
// Input order: 0 horizon, 1 hidden, 2 cell, 3 dec_x, 4 mote_id_cat,
// 5 fault_type_cat, 6 mote_fault_cat, 7 mote_embed, 8 W_ih0, 9 W_hh0,
// 10 b_ih0, 11 b_hh0, 12 W_ih1, 13 W_hh1, 14 b_ih1, 15 b_hh1
// ---------------------------------------------------------------------------
extern "C" void kernel_launch(void* const* d_in, const int* in_sizes, int n_in,
                              void* d_out, int out_size) {
    const float* hidden = (const float*)d_in[1];
    const float* cell   = (const float*)d_in[2];
    const float* dec_x  = (const float*)d_in[3];
    const int*   id1    = (const int*)d_in[4];
    const int*   id2    = (const int*)d_in[5];
    const int*   id3    = (const int*)d_in[6];
    const float* embed  = (const float*)d_in[7];
    const float* W_ih0  = (const float*)d_in[8];
    const float* W_hh0  = (const float*)d_in[9];
    const float* b_ih0  = (const float*)d_in[10];
    const float* b_hh0  = (const float*)d_in[11];
    const float* W_ih1  = (const float*)d_in[12];
    const float* W_hh1  = (const float*)d_in[13];
    const float* b_ih1  = (const float*)d_in[14];
    const float* b_hh1  = (const float*)d_in[15];
    float* out = (float*)d_out;

    prep_kernel<<<65, BLK>>>(hidden, cell, embed, W_ih0, W_hh0, b_ih0, b_hh0,
                             W_hh1, b_ih1, b_hh1);

    dim3 grid(NCHUNK, TT);
    decoder_kernel<<<grid, BLK>>>(dec_x, id1, id2, id3, W_ih0, W_ih1, out);
}

// round 10
// speedup vs baseline: 3.0276x; 1.0008x over previous
#include <cuda_runtime.h>
#include <cstdint>

// Problem constants (fixed shapes from setup_inputs)
#define TT 64
#define BB 4096
#define DD 32
#define HH 5
#define GG 20      // 4*H gates
#define VV 10
#define IN 128

#define BLK 256
#define NCHUNK (BB / BLK)           // 16 b-chunks

// Per-b precomputed terms (transposed [g][B] for coalesced access), L2-resident.
__device__ float g_hb0[GG * BB];
__device__ float g_hb1[GG * BB];
__device__ float g_c0[HH * BB];
__device__ float g_c1[HH * BB];
__device__ float g_lut[3 * VV * GG];   // [j][v][g] embedding->gate LUT

__device__ __forceinline__ float sigm(float v) {
    return __fdividef(1.0f, 1.0f + __expf(-v));
}
__device__ __forceinline__ float tanh_(float v) {
    return 1.0f - __fdividef(2.0f, __expf(2.0f * v) + 1.0f);
}

// ---- packed f32x2 helpers (sm_103a FFMA2 path) ----
__device__ __forceinline__ unsigned long long pack2(float a, float b) {
    unsigned long long r;
    asm("mov.b64 %0, {%1, %2};" : "=l"(r) : "f"(a), "f"(b));
    return r;
}
__device__ __forceinline__ void unpack2(unsigned long long v, float& a, float& b) {
    asm("mov.b64 {%0, %1}, %2;" : "=f"(a), "=f"(b) : "l"(v));
}
__device__ __forceinline__ void ffma2(unsigned long long& d,
                                      unsigned long long a,
                                      unsigned long long b) {
    asm("fma.rn.f32x2 %0, %1, %2, %0;" : "+l"(d) : "l"(a), "l"(b));
}
__device__ __forceinline__ unsigned long long d2u(double d) {
    return (unsigned long long)__double_as_longlong(d);
}

// ---------------------------------------------------------------------------
// Kernel 1: precompute. Blocks 0..63: (b, quarter) threads computing 5 gates
// of hb0 and 5 of hb1 each + cell transpose. Block 64: the embedding LUT.
// ---------------------------------------------------------------------------
__global__ void prep_kernel(const float* __restrict__ hidden,
                            const float* __restrict__ cell,
                            const float* __restrict__ embed,
                            const float* __restrict__ W_ih0,
                            const float* __restrict__ W_hh0,
                            const float* __restrict__ b_ih0,
                            const float* __restrict__ b_hh0,
                            const float* __restrict__ W_hh1,
                            const float* __restrict__ b_ih1,
                            const float* __restrict__ b_hh1) {
    if (blockIdx.x < 64) {
        int idx = blockIdx.x * BLK + threadIdx.x;
        int b = idx >> 2;             // 0..4095
        int q = idx & 3;              // gate quarter: gates [5q, 5q+5)
        float h0[HH], h1[HH];
#pragma unroll
        for (int k = 0; k < HH; k++) {
            h0[k] = hidden[b * HH + k];
            h1[k] = hidden[BB * HH + b * HH + k];
        }
#pragma unroll
        for (int j = 0; j < 5; j++) {
            int g = q * 5 + j;
            float s0 = b_ih0[g] + b_hh0[g];
            float s1 = b_ih1[g] + b_hh1[g];
#pragma unroll
            for (int k = 0; k < HH; k++) {
                s0 = fmaf(h0[k], W_hh0[g * HH + k], s0);
                s1 = fmaf(h1[k], W_hh1[g * HH + k], s1);
            }
            g_hb0[g * BB + b] = s0;
            g_hb1[g * BB + b] = s1;
        }
        if (q == 0) {
#pragma unroll
            for (int k = 0; k < HH; k++) {
                g_c0[k * BB + b] = cell[b * HH + k];
                g_c1[k * BB + b] = cell[BB * HH + b * HH + k];
            }
        }
    } else {
        for (int i = threadIdx.x; i < 3 * VV * GG; i += BLK) {
            int j = i / (VV * GG);
            int r = i - j * (VV * GG);
            int v = r / GG;
            int g = r - v * GG;
            const float* e = embed + v * DD;
            const float* w = W_ih0 + g * IN + DD + DD * j;
            float s = 0.0f;
#pragma unroll
            for (int k = 0; k < DD; k++) s = fmaf(e[k], w[k], s);
            g_lut[i] = s;   // layout [j][v][g]
        }
    }
}

// ---------------------------------------------------------------------------
// Kernel 2: main. One thread per (t, b). IPT=1, 64-reg cap -> 4 CTAs/SM.
// Layer-0 GEMM uses packed f32x2 FMA (k-packing): 320 FFMA2 instead of
// 640 FFMA. Scalar bias/LUT phase runs first, then packs into acc2 so the
// scalar and packed live sets never overlap.
//   blockIdx.x = b-chunk (16), blockIdx.y = t (64). 256 threads.
// ---------------------------------------------------------------------------
__global__ void __launch_bounds__(BLK, 4)
decoder_kernel(const float* __restrict__ dec_x,
               const int*   __restrict__ id1,
               const int*   __restrict__ id2,
               const int*   __restrict__ id3,
               const float* __restrict__ W_ih0,
               const float* __restrict__ W_ih1,
               float* __restrict__ out) {
    __shared__ __align__(16) float sWa[GG * DD];        // W_ih0[:,0:32] (f4 rows)
    __shared__ __align__(16) float sLut[3 * VV * GG];   // [j][v][g], 80B rows
    __shared__ __align__(16) float sW1t[HH * GG];       // W_ih1^T [k][g]
    __shared__ __align__(16) float sOut[BLK * HH];      // output staging

    const int tid = threadIdx.x;

    // ---- cooperative shared fill (copies only; LUT precomputed) ----
    for (int i = tid; i < GG * DD; i += BLK) {
        int g = i >> 5, k = i & 31;
        sWa[i] = W_ih0[g * IN + k];
    }
    for (int i = tid; i < HH * GG; i += BLK) {
        int k = i / GG, g = i - k * GG;
        sW1t[i] = W_ih1[g * HH + k];
    }
    for (int i = tid; i < 3 * VV * GG; i += BLK) sLut[i] = g_lut[i];
    __syncthreads();

    const int t  = blockIdx.y;
    const int b  = blockIdx.x * BLK + tid;
    const int tb = t * BB + b;

    // ---- scalar phase: pre[g] = hb0[g] + LUT adds ----
    float pre[GG];
#pragma unroll
    for (int g = 0; g < GG; g++) pre[g] = g_hb0[g * BB + b];
    {
        const int i1 = id1[tb], i2 = id2[tb], i3 = id3[tb];
        const float4* l1 = (const float4*)(sLut + (0 * VV + i1) * GG);
        const float4* l2 = (const float4*)(sLut + (1 * VV + i2) * GG);
        const float4* l3 = (const float4*)(sLut + (2 * VV + i3) * GG);
#pragma unroll
        for (int q = 0; q < GG / 4; q++) {
            float4 a = l1[q], c = l2[q], d = l3[q];
            pre[4 * q + 0] += a.x + c.x + d.x;
            pre[4 * q + 1] += a.y + c.y + d.y;
            pre[4 * q + 2] += a.z + c.z + d.z;
            pre[4 * q + 3] += a.w + c.w + d.w;
        }
    }

    // ---- pack accumulators: (pre, 0) ----
    unsigned long long acc2[GG];
#pragma unroll
    for (int g = 0; g < GG; g++) acc2[g] = pack2(pre[g], 0.0f);

    // ---- dec_x @ Wa^T : k-outer, packed f32x2; w LDS.128 broadcast ----
    {
        const double2* xp = (const double2*)(dec_x + (size_t)tb * DD);
#pragma unroll
        for (int q = 0; q < DD / 4; q++) {          // 4 k per iteration
            double2 x = xp[q];
            unsigned long long xa = d2u(x.x), xb = d2u(x.y);
            const double2* wp = (const double2*)sWa + q;  // stride DD/4 per gate
#pragma unroll
            for (int g = 0; g < GG; g++) {
                double2 w = wp[g * (DD / 4)];       // LDS.128, warp-uniform
                ffma2(acc2[g], xa, d2u(w.x));
                ffma2(acc2[g], xb, d2u(w.y));
            }
        }
    }

    // ---- horizontal sum ----
    float hg[GG];
#pragma unroll
    for (int g = 0; g < GG; g++) {
        float lo, hi;
        unpack2(acc2[g], lo, hi);
        hg[g] = lo + hi;
    }

    // ---- LSTM cell 0 (gate order i, f, g, o) ----
    float h1[HH];
#pragma unroll
    for (int k = 0; k < HH; k++) {
        float ig = sigm(hg[k]);
        float fg = sigm(hg[HH + k]);
        float gg = tanh_(hg[2 * HH + k]);
        float og = sigm(hg[3 * HH + k]);
        float c  = fmaf(fg, g_c0[k * BB + b], ig * gg);
        h1[k] = og * tanh_(c);
    }

    // ---- layer-1 gates: hb1 + h1 @ W_ih1^T (k-outer, f4 broadcast) ----
    float a1[GG];
#pragma unroll
    for (int g = 0; g < GG; g++) a1[g] = g_hb1[g * BB + b];
#pragma unroll
    for (int k = 0; k < HH; k++) {
        const float4* wp = (const float4*)(sW1t + k * GG);
        float hv = h1[k];
#pragma unroll
        for (int q = 0; q < GG / 4; q++) {
            float4 w = wp[q];
            a1[4 * q + 0] = fmaf(hv, w.x, a1[4 * q + 0]);
            a1[4 * q + 1] = fmaf(hv, w.y, a1[4 * q + 1]);
            a1[4 * q + 2] = fmaf(hv, w.z, a1[4 * q + 2]);
            a1[4 * q + 3] = fmaf(hv, w.w, a1[4 * q + 3]);
        }
    }

    // ---- LSTM cell 1 -> staged output ----
#pragma unroll
    for (int k = 0; k < HH; k++) {
        float ig = sigm(a1[k]);
        float fg = sigm(a1[HH + k]);
        float gg = tanh_(a1[2 * HH + k]);
        float og = sigm(a1[3 * HH + k]);
        float c  = fmaf(fg, g_c1[k * BB + b], ig * gg);
        sOut[tid * HH + k] = og * tanh_(c);
    }
    __syncthreads();

    // ---- coalesced store of the block's [256, 5] output slab ----
    float* ob = out + (size_t)t * BB * HH + (size_t)blockIdx.x * BLK * HH;
    for (int i = tid; i < BLK * HH; i += BLK) ob[i] = sOut[i];
}

// ---------------------------------------------------------------------------
// Launch
// Input order: 0 horizon, 1 hidden, 2 cell, 3 dec_x, 4 mote_id_cat,
// 5 fault_type_cat, 6 mote_fault_cat, 7 mote_embed, 8 W_ih0, 9 W_hh0,
// 10 b_ih0, 11 b_hh0, 12 W_ih1, 13 W_hh1, 14 b_ih1, 15 b_hh1
// ---------------------------------------------------------------------------
extern "C" void kernel_launch(void* const* d_in, const int* in_sizes, int n_in,
                              void* d_out, int out_size) {
    const float* hidden = (const float*)d_in[1];
    const float* cell   = (const float*)d_in[2];
    const float* dec_x  = (const float*)d_in[3];
    const int*   id1    = (const int*)d_in[4];
    const int*   id2    = (const int*)d_in[5];
    const int*   id3    = (const int*)d_in[6];
    const float* embed  = (const float*)d_in[7];
    const float* W_ih0  = (const float*)d_in[8];
    const float* W_hh0  = (const float*)d_in[9];
    const float* b_ih0  = (const float*)d_in[10];
    const float* b_hh0  = (const float*)d_in[11];
    const float* W_ih1  = (const float*)d_in[12];
    const float* W_hh1  = (const float*)d_in[13];
    const float* b_ih1  = (const float*)d_in[14];
    const float* b_hh1  = (const float*)d_in[15];
    float* out = (float*)d_out;

    prep_kernel<<<65, BLK>>>(hidden, cell, embed, W_ih0, W_hh0, b_ih0, b_hh0,
                             W_hh1, b_ih1, b_hh1);

    dim3 grid(NCHUNK, TT);
    decoder_kernel<<<grid, BLK>>>(dec_x, id1, id2, id3, W_ih0, W_ih1, out);
}